// round 13
// baseline (speedup 1.0000x reference)
#include <cuda_runtime.h>
#include <cuda_fp16.h>
#include <cstdint>

#define B_    16
#define C_    256
#define WIN   4096
#define OC_   256
#define KT    3
#define WOUT  4096
#define KTOT  768            // kk = k*256 + c
#define NCHUNK 24            // physical K chunks of 32
#define ROWB  80             // smem row stride bytes (32 fp16 + pad, conflict-free)
#define TILE_BYTES (128 * ROWB)          // 10240
#define NSTAGE_A 4
#define NBUF_B   3
#define PARAMS_BYTES 6144                // int i0[3][128], i1, float c0, c1
#define A_BYTES (NSTAGE_A * TILE_BYTES)  // 40960
#define B_BYTES (NBUF_B * TILE_BYTES)    // 30720
#define SMEM_BYTES (PARAMS_BYTES + A_BYTES + B_BYTES)  // 77824

// ---------------- scratch (static device globals; no allocation) ----------------
__device__ __align__(16) __half g_xth[(size_t)B_ * WIN * C_];     // [b][i][c] fp16
__device__ __align__(16) __half g_wh [OC_ * KTOT];                // [oc][kk]  fp16

// ---------------- helpers ----------------
__device__ __forceinline__ uint32_t smem_u32(const void* p) {
    uint32_t a;
    asm("{ .reg .u64 t; cvta.to.shared.u64 t, %1; cvt.u32.u64 %0, t; }" : "=r"(a) : "l"(p));
    return a;
}
__device__ __forceinline__ uint32_t h2_u32(__half2 h) {
    return *reinterpret_cast<uint32_t*>(&h);
}
__device__ __forceinline__ void cpa16(uint32_t dst, const void* src) {
    asm volatile("cp.async.cg.shared.global [%0], [%1], 16;" :: "r"(dst), "l"(src));
}
__device__ __forceinline__ void ldsm4(uint32_t& r0, uint32_t& r1, uint32_t& r2, uint32_t& r3,
                                      uint32_t addr) {
    asm volatile("ldmatrix.sync.aligned.m8n8.x4.shared.b16 {%0,%1,%2,%3}, [%4];"
                 : "=r"(r0), "=r"(r1), "=r"(r2), "=r"(r3) : "r"(addr));
}
__device__ __forceinline__ void mma16816(float* d, const uint32_t* a, const uint32_t* b) {
    asm volatile(
        "mma.sync.aligned.m16n8k16.row.col.f32.f16.f16.f32 "
        "{%0,%1,%2,%3}, {%4,%5,%6,%7}, {%8,%9}, {%0,%1,%2,%3};"
        : "+f"(d[0]), "+f"(d[1]), "+f"(d[2]), "+f"(d[3])
        : "r"(a[0]), "r"(a[1]), "r"(a[2]), "r"(a[3]), "r"(b[0]), "r"(b[1]));
}
__device__ __forceinline__ void sts16(uint32_t dst, uint4 v) {
    asm volatile("st.shared.v4.b32 [%0], {%1,%2,%3,%4};"
                 :: "r"(dst), "r"(v.x), "r"(v.y), "r"(v.z), "r"(v.w) : "memory");
}

// ---------------- kernel 1: transpose x[b][c][i] -> xth[b][i][c] (fp16) ----------------
__global__ void transpose_x(const float* __restrict__ x) {
    __shared__ float tile[32][33];
    int b = blockIdx.z;
    int i0 = blockIdx.x * 32, c0 = blockIdx.y * 32;
    int tx = threadIdx.x, ty = threadIdx.y;            // 32 x 8
    const float* xb = x + (size_t)b * C_ * WIN;
    #pragma unroll
    for (int r = 0; r < 32; r += 8)
        tile[ty + r][tx] = xb[(size_t)(c0 + ty + r) * WIN + i0 + tx];
    __syncthreads();
    __half* xtb = g_xth + (size_t)b * WIN * C_;
    #pragma unroll
    for (int r = 0; r < 32; r += 8)
        xtb[(size_t)(i0 + ty + r) * C_ + c0 + tx] = __float2half(tile[tx][ty + r]);
}

// ---------------- kernel 2: weight -> fp16, kk-major ----------------
__global__ void prep_weight(const float* __restrict__ weight) {
    int t = blockIdx.x * 256 + threadIdx.x;            // t = oc*768 + kk
    if (t >= OC_ * KTOT) return;
    int oc = t / KTOT, kk = t - oc * KTOT;
    int k = kk >> 8, c = kk & 255;
    g_wh[t] = __float2half(weight[oc * KTOT + c * KT + k]);
}

// ---------------- kernel 3: fused sample+GEMM ----------------
// D[256 oc x 4096 w] per batch. CTA tile 128x128; warp tile 64x32; K chunks of 32.
// B tile built in-kernel from gathered fp16 xth rows (modulated bilinear sampling).
__global__ __launch_bounds__(256, 2)
void gemm_kernel(const float* __restrict__ offset, const float* __restrict__ mask,
                 const float* __restrict__ bias, float* __restrict__ out) {
    extern __shared__ char smem[];
    uint32_t sbase = smem_u32(smem);
    int*   sIdx0 = (int*)smem;                         // [3][128]
    int*   sIdx1 = (int*)(smem + 1536);
    float* sC0   = (float*)(smem + 3072);
    float* sC1   = (float*)(smem + 4608);
    uint32_t aBase = sbase + PARAMS_BYTES;
    uint32_t bBase = sbase + PARAMS_BYTES + A_BYTES;

    int tid = threadIdx.x, lane = tid & 31, wid = tid >> 5;
    int wm = wid & 1, wn = wid >> 1;                   // warp grid 2 (m) x 4 (n)
    int nt = blockIdx.x, mt = blockIdx.y, bz = blockIdx.z;
    int mbase = mt * 128, nbase = nt * 128;

    // ---- sampling params for this CTA's 128 w rows x 3 taps ----
    for (int e = tid; e < KT * 128; e += 256) {
        int k = e >> 7, r = e & 127;
        int w = nbase + r;
        float off = offset[((size_t)bz * KT + k) * WOUT + w];
        float m   = mask  [((size_t)bz * KT + k) * WOUT + w];
        float p  = (float)(w - 1 + k) + off;           // stride=1, pad=1, dil=1
        float pf = floorf(p);
        int   i0 = (int)pf;
        float fr = p - pf;
        int   i1 = i0 + 1;
        float c0 = (1.0f - fr) * m;
        float c1 = fr * m;
        if (i0 < 0 || i0 >= WIN) { i0 = 0; c0 = 0.0f; }
        if (i1 < 0 || i1 >= WIN) { i1 = 0; c1 = 0.0f; }
        sIdx0[e] = i0; sIdx1[e] = i1; sC0[e] = c0; sC1[e] = c1;
    }
    __syncthreads();

    float acc[4][4][4];
    #pragma unroll
    for (int i = 0; i < 4; i++)
        #pragma unroll
        for (int j = 0; j < 4; j++)
            #pragma unroll
            for (int q = 0; q < 4; q++) acc[i][j][q] = 0.0f;

    const __half* xtb = g_xth + (size_t)bz * WIN * C_;
    int brow = tid >> 1, bhalf = tid & 1;              // 2 threads per w row, 16 c each

    auto build_B = [&](int pc) {
        int k  = pc >> 3;                              // 8 chunks of 32c per tap
        int cb = (pc & 7) * 32 + bhalf * 16;
        int e  = k * 128 + brow;
        int   i0 = sIdx0[e], i1 = sIdx1[e];
        float c0 = sC0[e],  c1 = sC1[e];
        const uint4* p0 = (const uint4*)(xtb + (size_t)i0 * C_ + cb);
        const uint4* p1 = (const uint4*)(xtb + (size_t)i1 * C_ + cb);
        uint4 q0a = p0[0], q0b = p0[1];                // 16 halves (row i0)
        uint4 q1a = p1[0], q1b = p1[1];                // 16 halves (row i1)
        uint32_t o[8];
        {
            const __half2* a2 = (const __half2*)&q0a;
            const __half2* b2 = (const __half2*)&q1a;
            #pragma unroll
            for (int j = 0; j < 4; j++) {
                float2 f = __half22float2(a2[j]);
                float2 g = __half22float2(b2[j]);
                o[j] = h2_u32(__floats2half2_rn(c0 * f.x + c1 * g.x,
                                                c0 * f.y + c1 * g.y));
            }
        }
        {
            const __half2* a2 = (const __half2*)&q0b;
            const __half2* b2 = (const __half2*)&q1b;
            #pragma unroll
            for (int j = 0; j < 4; j++) {
                float2 f = __half22float2(a2[j]);
                float2 g = __half22float2(b2[j]);
                o[4 + j] = h2_u32(__floats2half2_rn(c0 * f.x + c1 * g.x,
                                                    c0 * f.y + c1 * g.y));
            }
        }
        uint32_t dst = bBase + (uint32_t)((pc % NBUF_B) * TILE_BYTES)
                     + (uint32_t)(brow * ROWB + bhalf * 32);
        sts16(dst,      make_uint4(o[0], o[1], o[2], o[3]));
        sts16(dst + 16, make_uint4(o[4], o[5], o[6], o[7]));
    };

    auto issue_A = [&](int pc) {
        int kk0 = pc * 32;
        uint32_t st = aBase + (uint32_t)((pc & (NSTAGE_A - 1)) * TILE_BYTES);
        #pragma unroll
        for (int r = 0; r < 2; r++) {
            int id = tid + r * 256;                    // 0..511
            int row = id >> 2, seg = id & 3;           // 128 rows x 4 x 16B
            cpa16(st + (uint32_t)(row * ROWB + seg * 16),
                  g_wh + (size_t)(mbase + row) * KTOT + kk0 + seg * 8);
        }
        asm volatile("cp.async.commit_group;" ::: "memory");
    };

    // prologue
    issue_A(0); issue_A(1); issue_A(2);
    build_B(0);

    // per-lane ldmatrix addressing
    int arow = (lane & 7) + ((lane >> 3) & 1) * 8;     // A m16k16 x4
    int acol = ((lane >> 4) & 1) * 8;
    int brow8 = ((lane >> 4) & 1) * 8 + (lane & 7);    // B x4: lanes 16-31 -> +8 n-rows
    int bcol  = ((lane >> 3) & 1) * 8;

    for (int pc = 0; pc < NCHUNK; pc++) {
        if (pc + 1 < NCHUNK) build_B(pc + 1);          // writes buf (pc+1)%3; laggards
                                                       // read (pc-1)%3 — disjoint
        asm volatile("cp.async.wait_group 2;" ::: "memory");
        __syncthreads();
        if (pc + 3 < NCHUNK) issue_A(pc + 3);

        uint32_t sA = aBase + (uint32_t)((pc & (NSTAGE_A - 1)) * TILE_BYTES);
        uint32_t sB = bBase + (uint32_t)((pc % NBUF_B) * TILE_BYTES);

        #pragma unroll
        for (int ko = 0; ko < 32; ko += 16) {
            uint32_t bf[4][2];
            #pragma unroll
            for (int jj = 0; jj < 4; jj += 2) {
                uint32_t boff = (uint32_t)((wn * 32 + jj * 8 + brow8) * ROWB
                                           + (ko + bcol) * 2);
                ldsm4(bf[jj][0], bf[jj][1], bf[jj + 1][0], bf[jj + 1][1], sB + boff);
            }
            #pragma unroll
            for (int i = 0; i < 4; i++) {
                uint32_t aoff = (uint32_t)((wm * 64 + i * 16 + arow) * ROWB
                                           + (ko + acol) * 2);
                uint32_t a[4];
                ldsm4(a[0], a[1], a[2], a[3], sA + aoff);
                #pragma unroll
                for (int j = 0; j < 4; j++)
                    mma16816(acc[i][j], a, bf[j]);
            }
        }
    }

    // epilogue: add bias, write fp32
    int r4 = lane >> 2, c2 = (lane & 3) * 2;
    #pragma unroll
    for (int i = 0; i < 4; i++) {
        int oc0 = mbase + wm * 64 + i * 16 + r4;
        float bs0 = bias[oc0];
        float bs1 = bias[oc0 + 8];
        #pragma unroll
        for (int j = 0; j < 4; j++) {
            int w = nbase + wn * 32 + j * 8 + c2;
            float2 v0, v1;
            v0.x = acc[i][j][0] + bs0; v0.y = acc[i][j][1] + bs0;
            v1.x = acc[i][j][2] + bs1; v1.y = acc[i][j][3] + bs1;
            *(float2*)&out[((size_t)(bz * OC_ + oc0)) * WOUT + w]     = v0;
            *(float2*)&out[((size_t)(bz * OC_ + oc0 + 8)) * WOUT + w] = v1;
        }
    }
}

// ---------------- launch ----------------
extern "C" void kernel_launch(void* const* d_in, const int* in_sizes, int n_in,
                              void* d_out, int out_size) {
    const float* x      = (const float*)d_in[0];   // [16,256,4096]
    const float* weight = (const float*)d_in[1];   // [256,256,3]
    const float* offset = (const float*)d_in[2];   // [16,3,4096]
    const float* mask   = (const float*)d_in[3];   // [16,3,4096]
    const float* bias   = (const float*)d_in[4];   // [256]
    float* out = (float*)d_out;                    // [16,256,4096]

    cudaFuncSetAttribute(gemm_kernel, cudaFuncAttributeMaxDynamicSharedMemorySize,
                         SMEM_BYTES);

    {
        dim3 grid(WIN / 32, C_ / 32, B_);
        transpose_x<<<grid, dim3(32, 8)>>>(x);
    }
    prep_weight<<<(OC_ * KTOT + 255) / 256, 256>>>(weight);
    {
        dim3 grid(WOUT / 128, OC_ / 128, B_);      // 32 x 2 x 16 = 1024 CTAs
        gemm_kernel<<<grid, 256, SMEM_BYTES>>>(offset, mask, bias, out);
    }
}

// round 14
// speedup vs baseline: 1.1031x; 1.1031x over previous
#include <cuda_runtime.h>
#include <cuda_fp16.h>
#include <cstdint>

#define B_    16
#define C_    256
#define WIN   4096
#define OC_   256
#define KT    3
#define WOUT  4096
#define KTOT  768            // kk = k*256 + c
#define NCHUNK 24            // physical K chunks of 32
#define ROWB  80             // smem row stride bytes (32 fp16 + pad, conflict-free)
#define TILE_BYTES (128 * ROWB)          // 10240
#define STG_BYTES  (2 * TILE_BYTES)      // A + B = 20480
#define NSTAGE 4
#define SMEM_BYTES (NSTAGE * STG_BYTES)  // 81920

// ---------------- scratch (static device globals; no allocation) ----------------
__device__ __align__(16) __half g_xth[(size_t)B_ * WIN * C_];     // [b][i][c] fp16
__device__ __align__(16) __half g_sh [(size_t)B_ * WOUT * KTOT];  // [b][w][kk] fp16 samples
__device__ __align__(16) __half g_wh [OC_ * KTOT];                // [oc][kk]   fp16 weights

// ---------------- helpers ----------------
__device__ __forceinline__ uint32_t smem_u32(const void* p) {
    uint32_t a;
    asm("{ .reg .u64 t; cvta.to.shared.u64 t, %1; cvt.u32.u64 %0, t; }" : "=r"(a) : "l"(p));
    return a;
}
__device__ __forceinline__ uint32_t h2_u32(__half2 h) {
    return *reinterpret_cast<uint32_t*>(&h);
}
__device__ __forceinline__ void cpa16(uint32_t dst, const void* src) {
    asm volatile("cp.async.cg.shared.global [%0], [%1], 16;" :: "r"(dst), "l"(src));
}
__device__ __forceinline__ void ldsm4(uint32_t& r0, uint32_t& r1, uint32_t& r2, uint32_t& r3,
                                      uint32_t addr) {
    asm volatile("ldmatrix.sync.aligned.m8n8.x4.shared.b16 {%0,%1,%2,%3}, [%4];"
                 : "=r"(r0), "=r"(r1), "=r"(r2), "=r"(r3) : "r"(addr));
}
__device__ __forceinline__ void mma16816(float* d, const uint32_t* a, const uint32_t* b) {
    asm volatile(
        "mma.sync.aligned.m16n8k16.row.col.f32.f16.f16.f32 "
        "{%0,%1,%2,%3}, {%4,%5,%6,%7}, {%8,%9}, {%0,%1,%2,%3};"
        : "+f"(d[0]), "+f"(d[1]), "+f"(d[2]), "+f"(d[3])
        : "r"(a[0]), "r"(a[1]), "r"(a[2]), "r"(a[3]), "r"(b[0]), "r"(b[1]));
}

// ---------------- kernel 1: transpose x[b][c][i] -> xth[b][i][c] (fp16) ------------
__global__ void transpose_x(const float* __restrict__ x) {
    __shared__ float tile[32][33];
    int b = blockIdx.z;
    int i0 = blockIdx.x * 32, c0 = blockIdx.y * 32;
    int tx = threadIdx.x, ty = threadIdx.y;            // 32 x 8
    const float* xb = x + (size_t)b * C_ * WIN;
    #pragma unroll
    for (int r = 0; r < 32; r += 8)
        tile[ty + r][tx] = xb[(size_t)(c0 + ty + r) * WIN + i0 + tx];
    __syncthreads();
    __half* xtb = g_xth + (size_t)b * WIN * C_;
    #pragma unroll
    for (int r = 0; r < 32; r += 8)
        xtb[(size_t)(i0 + ty + r) * C_ + c0 + tx] = __float2half(tile[tx][ty + r]);
}

// ---------------- kernel 2: weight -> fp16, kk-major ----------------
__global__ void prep_weight(const float* __restrict__ weight) {
    int t = blockIdx.x * 256 + threadIdx.x;            // t = oc*768 + kk
    if (t >= OC_ * KTOT) return;
    int oc = t / KTOT, kk = t - oc * KTOT;
    int k = kk >> 8, c = kk & 255;
    g_wh[t] = __float2half(weight[oc * KTOT + c * KT + k]);
}

// ---------------- kernel 3: modulated bilinear sampling (fp16 in, fp16 out) --------
__global__ __launch_bounds__(256)
void sample_kernel(const float* __restrict__ offset, const float* __restrict__ mask) {
    int gw   = blockIdx.x * 8 + (threadIdx.x >> 5);    // one warp per (b,w)
    int lane = threadIdx.x & 31;
    int b = gw >> 12;
    int w = gw & 4095;
    const __half* xtb = g_xth + (size_t)b * WIN * C_;
    size_t srow = ((size_t)b * WOUT + w) * KTOT;
    #pragma unroll
    for (int k = 0; k < KT; k++) {
        float off = offset[((size_t)b * KT + k) * WOUT + w];
        float m   = mask  [((size_t)b * KT + k) * WOUT + w];
        float p  = (float)(w - 1 + k) + off;           // stride=1, pad=1, dil=1
        float pf = floorf(p);
        int   i0 = (int)pf;
        float fr = p - pf;
        int   i1 = i0 + 1;
        float c0 = (1.0f - fr) * m;
        float c1 = fr * m;
        if (i0 < 0 || i0 >= WIN) { i0 = 0; c0 = 0.0f; }
        if (i1 < 0 || i1 >= WIN) { i1 = 0; c1 = 0.0f; }
        // lane covers 8 channels: 16B per row
        uint4 q0 = ((const uint4*)(xtb + (size_t)i0 * C_))[lane];
        uint4 q1 = ((const uint4*)(xtb + (size_t)i1 * C_))[lane];
        const __half2* a2 = (const __half2*)&q0;
        const __half2* b2 = (const __half2*)&q1;
        uint32_t o[4];
        #pragma unroll
        for (int j = 0; j < 4; j++) {
            float2 f = __half22float2(a2[j]);
            float2 g = __half22float2(b2[j]);
            o[j] = h2_u32(__floats2half2_rn(c0 * f.x + c1 * g.x,
                                            c0 * f.y + c1 * g.y));
        }
        *(uint4*)(g_sh + srow + k * 256 + lane * 8) = make_uint4(o[0], o[1], o[2], o[3]);
    }
}

// ---------------- kernel 4: GEMM via mma.sync fp16, 4-stage cp.async pipeline ------
// D[256 oc x 4096 w] per batch. CTA tile 128x128; warp tile 64x32; K chunks of 32.
__global__ __launch_bounds__(256, 2)
void gemm_kernel(const float* __restrict__ bias, float* __restrict__ out) {
    extern __shared__ char smem[];
    uint32_t sbase = smem_u32(smem);
    int tid = threadIdx.x, lane = tid & 31, wid = tid >> 5;
    int wm = wid & 1, wn = wid >> 1;                   // warp grid 2 (m) x 4 (n)
    int nt = blockIdx.x, mt = blockIdx.y, bz = blockIdx.z;
    int mbase = mt * 128, nbase = nt * 128;

    float acc[4][4][4];
    #pragma unroll
    for (int i = 0; i < 4; i++)
        #pragma unroll
        for (int j = 0; j < 4; j++)
            #pragma unroll
            for (int q = 0; q < 4; q++) acc[i][j][q] = 0.0f;

    auto issue = [&](int pc) {
        int kk0 = pc * 32;
        uint32_t st = sbase + (uint32_t)(pc & (NSTAGE - 1)) * STG_BYTES;
        #pragma unroll
        for (int r = 0; r < 2; r++) {
            int id = tid + r * 256;                    // 0..511
            int row = id >> 2, seg = id & 3;           // 128 rows x 4 x 16B
            uint32_t off = (uint32_t)(row * ROWB + seg * 16);
            cpa16(st + off,
                  g_wh + (size_t)(mbase + row) * KTOT + kk0 + seg * 8);
            cpa16(st + TILE_BYTES + off,
                  g_sh + ((size_t)bz * WOUT + nbase + row) * KTOT + kk0 + seg * 8);
        }
        asm volatile("cp.async.commit_group;" ::: "memory");
    };

    // prologue: 3 stages in flight
    issue(0); issue(1); issue(2);

    // per-lane ldmatrix addressing
    int arow = (lane & 7) + ((lane >> 3) & 1) * 8;     // A m16k16 x4
    int acol = ((lane >> 4) & 1) * 8;
    int brow8 = ((lane >> 4) & 1) * 8 + (lane & 7);    // B x4: lanes 16-31 -> +8 n-rows
    int bcol  = ((lane >> 3) & 1) * 8;

    for (int pc = 0; pc < NCHUNK; pc++) {
        asm volatile("cp.async.wait_group 2;" ::: "memory");
        __syncthreads();

        uint32_t st = sbase + (uint32_t)(pc & (NSTAGE - 1)) * STG_BYTES;
        uint32_t sA = st, sB = st + TILE_BYTES;

        #pragma unroll
        for (int ko = 0; ko < 32; ko += 16) {
            uint32_t bf[4][2];
            #pragma unroll
            for (int jj = 0; jj < 4; jj += 2) {
                uint32_t boff = (uint32_t)((wn * 32 + jj * 8 + brow8) * ROWB
                                           + (ko + bcol) * 2);
                ldsm4(bf[jj][0], bf[jj][1], bf[jj + 1][0], bf[jj + 1][1], sB + boff);
            }
            #pragma unroll
            for (int i = 0; i < 4; i++) {
                uint32_t aoff = (uint32_t)((wm * 64 + i * 16 + arow) * ROWB
                                           + (ko + acol) * 2);
                uint32_t a[4];
                ldsm4(a[0], a[1], a[2], a[3], sA + aoff);
                #pragma unroll
                for (int j = 0; j < 4; j++)
                    mma16816(acc[i][j], a, bf[j]);
            }
        }
        __syncthreads();

        if (pc + 3 < NCHUNK) issue(pc + 3);
    }

    // epilogue: add bias, write fp32
    int r4 = lane >> 2, c2 = (lane & 3) * 2;
    #pragma unroll
    for (int i = 0; i < 4; i++) {
        int oc0 = mbase + wm * 64 + i * 16 + r4;
        float bs0 = bias[oc0];
        float bs1 = bias[oc0 + 8];
        #pragma unroll
        for (int j = 0; j < 4; j++) {
            int w = nbase + wn * 32 + j * 8 + c2;
            float2 v0, v1;
            v0.x = acc[i][j][0] + bs0; v0.y = acc[i][j][1] + bs0;
            v1.x = acc[i][j][2] + bs1; v1.y = acc[i][j][3] + bs1;
            *(float2*)&out[((size_t)(bz * OC_ + oc0)) * WOUT + w]     = v0;
            *(float2*)&out[((size_t)(bz * OC_ + oc0 + 8)) * WOUT + w] = v1;
        }
    }
}

// ---------------- launch ----------------
extern "C" void kernel_launch(void* const* d_in, const int* in_sizes, int n_in,
                              void* d_out, int out_size) {
    const float* x      = (const float*)d_in[0];   // [16,256,4096]
    const float* weight = (const float*)d_in[1];   // [256,256,3]
    const float* offset = (const float*)d_in[2];   // [16,3,4096]
    const float* mask   = (const float*)d_in[3];   // [16,3,4096]
    const float* bias   = (const float*)d_in[4];   // [256]
    float* out = (float*)d_out;                    // [16,256,4096]

    cudaFuncSetAttribute(gemm_kernel, cudaFuncAttributeMaxDynamicSharedMemorySize,
                         SMEM_BYTES);

    {
        dim3 grid(WIN / 32, C_ / 32, B_);
        transpose_x<<<grid, dim3(32, 8)>>>(x);
    }
    prep_weight<<<(OC_ * KTOT + 255) / 256, 256>>>(weight);
    sample_kernel<<<B_ * WOUT / 8, 256>>>(offset, mask);
    {
        dim3 grid(WOUT / 128, OC_ / 128, B_);      // 32 x 2 x 16 = 1024 CTAs
        gemm_kernel<<<grid, 256, SMEM_BYTES>>>(bias, out);
    }
}